// round 7
// baseline (speedup 1.0000x reference)
#include <cuda_runtime.h>
#include <cstdint>
#include <math.h>

#define BATCH   2048
#define IN_DIM  512
#define NUM_OUT 256

#define BM 64
#define BN 128
#define BK 16
#define NTHREADS 128
#define KSPLIT 8
#define KCHUNK (IN_DIM / KSPLIT)    // 64
#define NSTEPS (KCHUNK / BK)        // 4

typedef unsigned long long ull;

// g_w[k][o] = -sigmoid(5 * W_raw[o][k]); [512][256] floats, 512 KB.
__device__ float g_w[IN_DIM * NUM_OUT];
// Partial products per K-chunk: 16 MB
__device__ float g_part[KSPLIT][BATCH * NUM_OUT];

// Flat precompute: linear index i = o*512 + k is exactly Wraw's layout ->
// fully coalesced loads; scattered 4B stores are fire-and-forget.
__global__ void precompute_kernel(const float* __restrict__ Wraw) {
    int i = blockIdx.x * blockDim.x + threadIdx.x;   // 0 .. 131071
    if (i < NUM_OUT * IN_DIM) {
        int o = i >> 9;        // i / 512
        int k = i & 511;       // i % 512
        float v = Wraw[i];
        float w = 1.0f / (1.0f + __expf(-5.0f * v));
        g_w[k * NUM_OUT + o] = -w;
    }
}

__device__ __forceinline__ ull ffma2(ull a, ull b, ull c) {
    ull d;
    asm("fma.rn.f32x2 %0, %1, %2, %3;" : "=l"(d) : "l"(a), "l"(b), "l"(c));
    return d;
}
__device__ __forceinline__ ull fmul2(ull a, ull b) {
    ull d;
    asm("mul.rn.f32x2 %0, %1, %2;" : "=l"(d) : "l"(a), "l"(b));
    return d;
}
__device__ __forceinline__ void cp_async16(uint32_t smem, const void* gptr) {
    asm volatile("cp.async.cg.shared.global [%0], [%1], 16;" :: "r"(smem), "l"(gptr));
}

// 64(M) x 128(N) tile per CTA over one 64-K chunk. Thread tile 8x8.
// Accumulator packs two adjacent N-cols per f32x2 (no w duplication).
// x stored duplicated in smem: xs[k][2*row] = xs[k][2*row+1] = 1-x.
// w row piece-permuted: 16B piece p -> phys chunk (p even ? p/2 : 16+p/2),
// so each thread's two LDS.128 hit contiguous 256B halves (conflict-free).
__global__ void __launch_bounds__(NTHREADS, 4)
logic_kernel(const float* __restrict__ x) {
    __shared__ __align__(16) float xs[2][BK][2 * BM + 4];   // 132 floats/row
    __shared__ __align__(16) float ws[2][BK][BN + 4];       // 132 floats/row

    const int tid = threadIdx.x;
    const int bm0 = blockIdx.x * BM;
    const int bn  = blockIdx.y;          // 0..1
    const int kz  = blockIdx.z;          // K-chunk
    const int kbase = kz * KCHUNK;

    const int cg = tid & 15;   // col-group: 8 cols each
    const int rg = tid >> 4;   // row-group: 8 rows each

    // x staging: row xm (0..63), k-half xq (8 k's each)
    const int xm = tid & 63;
    const int xq = tid >> 6;   // 0 or 1

    const ull ONE2 = 0x3F8000003F800000ULL;
    ull acc[8][4];
#pragma unroll
    for (int i = 0; i < 8; ++i)
#pragma unroll
        for (int j = 0; j < 4; ++j) acc[i][j] = ONE2;

    const float* xrow = x + (ull)(bm0 + xm) * IN_DIM + kbase + xq * 8;

    // ---------------- prologue: fill buffer 0 ----------------
    {
        float4 a = *reinterpret_cast<const float4*>(xrow + 0);
        float4 b = *reinterpret_cast<const float4*>(xrow + 4);
#pragma unroll
        for (int c = 0; c < 4; ++c) {
            int idx = c * 128 + tid;
            int k   = idx >> 5;        // 0..15
            int q   = idx & 31;        // 16B chunk within row
            int goff = ((q & 15) * 8 + (q >> 4) * 4);
            const float* src = g_w + (ull)(kbase + k) * NUM_OUT + bn * BN + goff;
            cp_async16((uint32_t)__cvta_generic_to_shared(&ws[0][k][q * 4]), src);
        }
        asm volatile("cp.async.commit_group;" ::: "memory");
        int kb = xq * 8;
        float2 p;
#define XDUP(slot, val) p.x = 1.0f - (val); p.y = p.x; \
        *reinterpret_cast<float2*>(&xs[0][kb + slot][2 * xm]) = p;
        XDUP(0, a.x) XDUP(1, a.y) XDUP(2, a.z) XDUP(3, a.w)
        XDUP(4, b.x) XDUP(5, b.y) XDUP(6, b.z) XDUP(7, b.w)
#undef XDUP
    }

    // ---------------- main loop ----------------
    for (int step = 0; step < NSTEPS; ++step) {
        const int buf  = step & 1;
        const int nbuf = buf ^ 1;
        const bool more = (step + 1 < NSTEPS);

        __syncthreads();   // compute(step-1) done; x STS(step) visible

        float4 a, b;
        if (more) {
            const float* xp = xrow + (step + 1) * BK;
            a = *reinterpret_cast<const float4*>(xp + 0);
            b = *reinterpret_cast<const float4*>(xp + 4);
            int k0 = kbase + (step + 1) * BK;
#pragma unroll
            for (int c = 0; c < 4; ++c) {
                int idx = c * 128 + tid;
                int k   = idx >> 5;
                int q   = idx & 31;
                int goff = ((q & 15) * 8 + (q >> 4) * 4);
                const float* src = g_w + (ull)(k0 + k) * NUM_OUT + bn * BN + goff;
                cp_async16((uint32_t)__cvta_generic_to_shared(&ws[nbuf][k][q * 4]), src);
            }
        }
        asm volatile("cp.async.commit_group;" ::: "memory");
        asm volatile("cp.async.wait_group 1;" ::: "memory");
        __syncthreads();   // ws[buf] fully landed

        // ---------- compute on buf ----------
#pragma unroll
        for (int k = 0; k < BK; ++k) {
            ulonglong2 xa = *reinterpret_cast<const ulonglong2*>(&xs[buf][k][rg * 16]);
            ulonglong2 xb = *reinterpret_cast<const ulonglong2*>(&xs[buf][k][rg * 16 + 4]);
            ulonglong2 xc = *reinterpret_cast<const ulonglong2*>(&xs[buf][k][rg * 16 + 8]);
            ulonglong2 xd = *reinterpret_cast<const ulonglong2*>(&xs[buf][k][rg * 16 + 12]);
            ulonglong2 wa = *reinterpret_cast<const ulonglong2*>(&ws[buf][k][cg * 4]);
            ulonglong2 wb = *reinterpret_cast<const ulonglong2*>(&ws[buf][k][64 + cg * 4]);
            ull xv[8] = {xa.x, xa.y, xb.x, xb.y, xc.x, xc.y, xd.x, xd.y};
            ull wv[4] = {wa.x, wa.y, wb.x, wb.y};
#pragma unroll
            for (int i = 0; i < 8; ++i) {
#pragma unroll
                for (int j = 0; j < 4; ++j) {
                    ull z = ffma2(wv[j], xv[i], ONE2);   // (1-w*t, 1-w*t)
                    acc[i][j] = fmul2(acc[i][j], z);
                }
            }
        }

        if (more) {
            int kb = xq * 8;
            float2 p;
#define XDUP(slot, val) p.x = 1.0f - (val); p.y = p.x; \
            *reinterpret_cast<float2*>(&xs[nbuf][kb + slot][2 * xm]) = p;
            XDUP(0, a.x) XDUP(1, a.y) XDUP(2, a.z) XDUP(3, a.w)
            XDUP(4, b.x) XDUP(5, b.y) XDUP(6, b.z) XDUP(7, b.w)
#undef XDUP
        }
    }

    // ---------------- epilogue: write partial products ----------------
    float* orow = g_part[kz] + (ull)(bm0 + rg * 8) * NUM_OUT + bn * BN + cg * 8;
#pragma unroll
    for (int i = 0; i < 8; ++i) {
        float4 v0, v1;
        v0.x = __uint_as_float((unsigned)(acc[i][0]));
        v0.y = __uint_as_float((unsigned)(acc[i][0] >> 32));
        v0.z = __uint_as_float((unsigned)(acc[i][1]));
        v0.w = __uint_as_float((unsigned)(acc[i][1] >> 32));
        v1.x = __uint_as_float((unsigned)(acc[i][2]));
        v1.y = __uint_as_float((unsigned)(acc[i][2] >> 32));
        v1.z = __uint_as_float((unsigned)(acc[i][3]));
        v1.w = __uint_as_float((unsigned)(acc[i][3] >> 32));
        *reinterpret_cast<float4*>(orow + (ull)i * NUM_OUT)     = v0;
        *reinterpret_cast<float4*>(orow + (ull)i * NUM_OUT + 4) = v1;
    }
}

// out = product of 8 partials elementwise (float4-vectorized, tree order)
__global__ void combine_kernel(float* __restrict__ out) {
    int i = blockIdx.x * blockDim.x + threadIdx.x;
    if (i < (BATCH * NUM_OUT) / 4) {
        float4 p0 = reinterpret_cast<const float4*>(g_part[0])[i];
        float4 p1 = reinterpret_cast<const float4*>(g_part[1])[i];
        float4 p2 = reinterpret_cast<const float4*>(g_part[2])[i];
        float4 p3 = reinterpret_cast<const float4*>(g_part[3])[i];
        float4 p4 = reinterpret_cast<const float4*>(g_part[4])[i];
        float4 p5 = reinterpret_cast<const float4*>(g_part[5])[i];
        float4 p6 = reinterpret_cast<const float4*>(g_part[6])[i];
        float4 p7 = reinterpret_cast<const float4*>(g_part[7])[i];
        float4 v;
        v.x = ((p0.x * p1.x) * (p2.x * p3.x)) * ((p4.x * p5.x) * (p6.x * p7.x));
        v.y = ((p0.y * p1.y) * (p2.y * p3.y)) * ((p4.y * p5.y) * (p6.y * p7.y));
        v.z = ((p0.z * p1.z) * (p2.z * p3.z)) * ((p4.z * p5.z) * (p6.z * p7.z));
        v.w = ((p0.w * p1.w) * (p2.w * p3.w)) * ((p4.w * p5.w) * (p6.w * p7.w));
        reinterpret_cast<float4*>(out)[i] = v;
    }
}

extern "C" void kernel_launch(void* const* d_in, const int* in_sizes, int n_in,
                              void* d_out, int out_size) {
    const float* x    = (const float*)d_in[0];   // [2048, 512]
    const float* Wraw = (const float*)d_in[1];   // [256, 512]
    float* out        = (float*)d_out;           // [2048, 256]

    precompute_kernel<<<(NUM_OUT * IN_DIM + 255) / 256, 256>>>(Wraw);

    dim3 grid(BATCH / BM, NUM_OUT / BN, KSPLIT); // 32 x 2 x 8 = 512 CTAs
    logic_kernel<<<grid, NTHREADS>>>(x);

    combine_kernel<<<(BATCH * NUM_OUT / 4 + 255) / 256, 256>>>(out);
}

// round 8
// speedup vs baseline: 1.0116x; 1.0116x over previous
#include <cuda_runtime.h>
#include <cstdint>
#include <math.h>

#define BATCH   2048
#define IN_DIM  512
#define NUM_OUT 256

#define BM 64
#define BN 128
#define BK 16
#define NTHREADS 128
#define KSPLIT 8
#define KCHUNK (IN_DIM / KSPLIT)    // 64
#define NSTEPS (KCHUNK / BK)        // 4

typedef unsigned long long ull;

// g_w[k][o] = -sigmoid(5 * W_raw[o][k]); [512][256] floats, 512 KB.
__device__ float g_w[IN_DIM * NUM_OUT];
// Partial products per K-chunk: 16 MB
__device__ float g_part[KSPLIT][BATCH * NUM_OUT];

// Flat precompute: linear index i = o*512 + k is exactly Wraw's layout ->
// fully coalesced loads; scattered 4B stores are fire-and-forget.
__global__ void precompute_kernel(const float* __restrict__ Wraw) {
    int i = blockIdx.x * blockDim.x + threadIdx.x;   // 0 .. 131071
    if (i < NUM_OUT * IN_DIM) {
        int o = i >> 9;        // i / 512
        int k = i & 511;       // i % 512
        float v = Wraw[i];
        float w = 1.0f / (1.0f + __expf(-5.0f * v));
        g_w[k * NUM_OUT + o] = -w;
    }
}

__device__ __forceinline__ ull ffma2(ull a, ull b, ull c) {
    ull d;
    asm("fma.rn.f32x2 %0, %1, %2, %3;" : "=l"(d) : "l"(a), "l"(b), "l"(c));
    return d;
}
__device__ __forceinline__ ull fmul2(ull a, ull b) {
    ull d;
    asm("mul.rn.f32x2 %0, %1, %2;" : "=l"(d) : "l"(a), "l"(b));
    return d;
}
__device__ __forceinline__ void cp_async16(uint32_t smem, const void* gptr) {
    asm volatile("cp.async.cg.shared.global [%0], [%1], 16;" :: "r"(smem), "l"(gptr));
}

// 64(M) x 128(N) tile per CTA over one 64-K chunk. Thread tile 8x8.
// Accumulator packs two adjacent N-cols per f32x2 (no w duplication).
// x stored duplicated in smem: xs[k][2*row] = xs[k][2*row+1] = 1-x.
// w row piece-permuted: 16B piece p -> phys chunk (p even ? p/2 : 16+p/2),
// so each thread's two LDS.128 hit contiguous 256B halves (conflict-free).
__global__ void __launch_bounds__(NTHREADS, 4)
logic_kernel(const float* __restrict__ x) {
    __shared__ __align__(16) float xs[2][BK][2 * BM + 4];   // 132 floats/row
    __shared__ __align__(16) float ws[2][BK][BN + 4];       // 132 floats/row

    const int tid = threadIdx.x;
    const int bm0 = blockIdx.x * BM;
    const int bn  = blockIdx.y;          // 0..1
    const int kz  = blockIdx.z;          // K-chunk
    const int kbase = kz * KCHUNK;

    const int cg = tid & 15;   // col-group: 8 cols each
    const int rg = tid >> 4;   // row-group: 8 rows each

    // x staging: row xm (0..63), k-half xq (8 k's each)
    const int xm = tid & 63;
    const int xq = tid >> 6;   // 0 or 1

    const ull ONE2 = 0x3F8000003F800000ULL;
    ull acc[8][4];
#pragma unroll
    for (int i = 0; i < 8; ++i)
#pragma unroll
        for (int j = 0; j < 4; ++j) acc[i][j] = ONE2;

    const float* xrow = x + (ull)(bm0 + xm) * IN_DIM + kbase + xq * 8;

    // ---------------- prologue: fill buffer 0 ----------------
    {
        float4 a = *reinterpret_cast<const float4*>(xrow + 0);
        float4 b = *reinterpret_cast<const float4*>(xrow + 4);
#pragma unroll
        for (int c = 0; c < 4; ++c) {
            int idx = c * 128 + tid;
            int k   = idx >> 5;        // 0..15
            int q   = idx & 31;        // 16B chunk within row
            int goff = ((q & 15) * 8 + (q >> 4) * 4);
            const float* src = g_w + (ull)(kbase + k) * NUM_OUT + bn * BN + goff;
            cp_async16((uint32_t)__cvta_generic_to_shared(&ws[0][k][q * 4]), src);
        }
        asm volatile("cp.async.commit_group;" ::: "memory");
        int kb = xq * 8;
        float2 p;
#define XDUP(slot, val) p.x = 1.0f - (val); p.y = p.x; \
        *reinterpret_cast<float2*>(&xs[0][kb + slot][2 * xm]) = p;
        XDUP(0, a.x) XDUP(1, a.y) XDUP(2, a.z) XDUP(3, a.w)
        XDUP(4, b.x) XDUP(5, b.y) XDUP(6, b.z) XDUP(7, b.w)
#undef XDUP
    }

    // ---------------- main loop ----------------
    for (int step = 0; step < NSTEPS; ++step) {
        const int buf  = step & 1;
        const int nbuf = buf ^ 1;
        const bool more = (step + 1 < NSTEPS);

        __syncthreads();   // compute(step-1) done; x STS(step) visible

        float4 a, b;
        if (more) {
            const float* xp = xrow + (step + 1) * BK;
            a = *reinterpret_cast<const float4*>(xp + 0);
            b = *reinterpret_cast<const float4*>(xp + 4);
            int k0 = kbase + (step + 1) * BK;
#pragma unroll
            for (int c = 0; c < 4; ++c) {
                int idx = c * 128 + tid;
                int k   = idx >> 5;
                int q   = idx & 31;
                int goff = ((q & 15) * 8 + (q >> 4) * 4);
                const float* src = g_w + (ull)(k0 + k) * NUM_OUT + bn * BN + goff;
                cp_async16((uint32_t)__cvta_generic_to_shared(&ws[nbuf][k][q * 4]), src);
            }
        }
        asm volatile("cp.async.commit_group;" ::: "memory");
        asm volatile("cp.async.wait_group 1;" ::: "memory");
        __syncthreads();   // ws[buf] fully landed

        // ---------- compute on buf ----------
#pragma unroll
        for (int k = 0; k < BK; ++k) {
            ulonglong2 xa = *reinterpret_cast<const ulonglong2*>(&xs[buf][k][rg * 16]);
            ulonglong2 xb = *reinterpret_cast<const ulonglong2*>(&xs[buf][k][rg * 16 + 4]);
            ulonglong2 xc = *reinterpret_cast<const ulonglong2*>(&xs[buf][k][rg * 16 + 8]);
            ulonglong2 xd = *reinterpret_cast<const ulonglong2*>(&xs[buf][k][rg * 16 + 12]);
            ulonglong2 wa = *reinterpret_cast<const ulonglong2*>(&ws[buf][k][cg * 4]);
            ulonglong2 wb = *reinterpret_cast<const ulonglong2*>(&ws[buf][k][64 + cg * 4]);
            ull xv[8] = {xa.x, xa.y, xb.x, xb.y, xc.x, xc.y, xd.x, xd.y};
            ull wv[4] = {wa.x, wa.y, wb.x, wb.y};
#pragma unroll
            for (int i = 0; i < 8; ++i) {
#pragma unroll
                for (int j = 0; j < 4; ++j) {
                    ull z = ffma2(wv[j], xv[i], ONE2);   // (1-w*t, 1-w*t)
                    acc[i][j] = fmul2(acc[i][j], z);
                }
            }
        }

        if (more) {
            int kb = xq * 8;
            float2 p;
#define XDUP(slot, val) p.x = 1.0f - (val); p.y = p.x; \
            *reinterpret_cast<float2*>(&xs[nbuf][kb + slot][2 * xm]) = p;
            XDUP(0, a.x) XDUP(1, a.y) XDUP(2, a.z) XDUP(3, a.w)
            XDUP(4, b.x) XDUP(5, b.y) XDUP(6, b.z) XDUP(7, b.w)
#undef XDUP
        }
    }

    // ---------------- epilogue: write partial products ----------------
    float* orow = g_part[kz] + (ull)(bm0 + rg * 8) * NUM_OUT + bn * BN + cg * 8;
#pragma unroll
    for (int i = 0; i < 8; ++i) {
        float4 v0, v1;
        v0.x = __uint_as_float((unsigned)(acc[i][0]));
        v0.y = __uint_as_float((unsigned)(acc[i][0] >> 32));
        v0.z = __uint_as_float((unsigned)(acc[i][1]));
        v0.w = __uint_as_float((unsigned)(acc[i][1] >> 32));
        v1.x = __uint_as_float((unsigned)(acc[i][2]));
        v1.y = __uint_as_float((unsigned)(acc[i][2] >> 32));
        v1.z = __uint_as_float((unsigned)(acc[i][3]));
        v1.w = __uint_as_float((unsigned)(acc[i][3] >> 32));
        *reinterpret_cast<float4*>(orow + (ull)i * NUM_OUT)     = v0;
        *reinterpret_cast<float4*>(orow + (ull)i * NUM_OUT + 4) = v1;
    }
}

// out = product of 8 partials elementwise (float4-vectorized, tree order)
__global__ void combine_kernel(float* __restrict__ out) {
    int i = blockIdx.x * blockDim.x + threadIdx.x;
    if (i < (BATCH * NUM_OUT) / 4) {
        float4 p0 = reinterpret_cast<const float4*>(g_part[0])[i];
        float4 p1 = reinterpret_cast<const float4*>(g_part[1])[i];
        float4 p2 = reinterpret_cast<const float4*>(g_part[2])[i];
        float4 p3 = reinterpret_cast<const float4*>(g_part[3])[i];
        float4 p4 = reinterpret_cast<const float4*>(g_part[4])[i];
        float4 p5 = reinterpret_cast<const float4*>(g_part[5])[i];
        float4 p6 = reinterpret_cast<const float4*>(g_part[6])[i];
        float4 p7 = reinterpret_cast<const float4*>(g_part[7])[i];
        float4 v;
        v.x = ((p0.x * p1.x) * (p2.x * p3.x)) * ((p4.x * p5.x) * (p6.x * p7.x));
        v.y = ((p0.y * p1.y) * (p2.y * p3.y)) * ((p4.y * p5.y) * (p6.y * p7.y));
        v.z = ((p0.z * p1.z) * (p2.z * p3.z)) * ((p4.z * p5.z) * (p6.z * p7.z));
        v.w = ((p0.w * p1.w) * (p2.w * p3.w)) * ((p4.w * p5.w) * (p6.w * p7.w));
        reinterpret_cast<float4*>(out)[i] = v;
    }
}

extern "C" void kernel_launch(void* const* d_in, const int* in_sizes, int n_in,
                              void* d_out, int out_size) {
    const float* x    = (const float*)d_in[0];   // [2048, 512]
    const float* Wraw = (const float*)d_in[1];   // [256, 512]
    float* out        = (float*)d_out;           // [2048, 256]

    precompute_kernel<<<(NUM_OUT * IN_DIM + 255) / 256, 256>>>(Wraw);

    dim3 grid(BATCH / BM, NUM_OUT / BN, KSPLIT); // 32 x 2 x 8 = 512 CTAs
    logic_kernel<<<grid, NTHREADS>>>(x);

    combine_kernel<<<(BATCH * NUM_OUT / 4 + 255) / 256, 256>>>(out);
}